// round 16
// baseline (speedup 1.0000x reference)
#include <cuda_runtime.h>
#include <cuda_bf16.h>
#include <cstdint>

// Problem constants
#define B_   4
#define T_   2048
#define C_   1024
#define H_   128
#define BT_  (B_ * T_)

// ---------------------------------------------------------------------------
// Scratch (__device__ globals per alloc rules)
// ---------------------------------------------------------------------------
__device__ __nv_bfloat16 g_qhi[BT_ * H_];
__device__ __nv_bfloat16 g_qlo[BT_ * H_];
__device__ __nv_bfloat16 g_khi[BT_ * H_];
__device__ __nv_bfloat16 g_klo[BT_ * H_];
__device__ __nv_bfloat16 g_vhi[BT_ * H_];
__device__ __nv_bfloat16 g_vlo[BT_ * H_];
__device__ __nv_bfloat16 g_wt_hi[3 * H_ * C_];
__device__ __nv_bfloat16 g_wt_lo[3 * H_ * C_];
__device__ float  g_po[2 * BT_ * H_];
__device__ float2 g_ml[2 * BT_];

// Work-unit table: 48 units per batch, globally sorted by descending tile
// count. entry = qt | (t0 << 8) | (t1 << 16); unit covers KV tiles [t0, t1).
__device__ const uint32_t g_units[48] = {
    31u | (0u<<8) | (16u<<16), 31u | (16u<<8) | (32u<<16), 30u | (15u<<8) | (31u<<16), 15u | (0u<<8) | (16u<<16),
    30u | (0u<<8) | (15u<<16), 29u | (0u<<8) | (15u<<16), 29u | (15u<<8) | (30u<<16), 28u | (14u<<8) | (29u<<16), 14u | (0u<<8) | (15u<<16),
    28u | (0u<<8) | (14u<<16), 27u | (0u<<8) | (14u<<16), 27u | (14u<<8) | (28u<<16), 26u | (13u<<8) | (27u<<16), 13u | (0u<<8) | (14u<<16),
    26u | (0u<<8) | (13u<<16), 25u | (0u<<8) | (13u<<16), 25u | (13u<<8) | (26u<<16), 24u | (12u<<8) | (25u<<16), 12u | (0u<<8) | (13u<<16),
    24u | (0u<<8) | (12u<<16), 23u | (0u<<8) | (12u<<16), 23u | (12u<<8) | (24u<<16), 22u | (11u<<8) | (23u<<16), 11u | (0u<<8) | (12u<<16),
    22u | (0u<<8) | (11u<<16), 21u | (0u<<8) | (11u<<16), 21u | (11u<<8) | (22u<<16), 20u | (10u<<8) | (21u<<16), 10u | (0u<<8) | (11u<<16),
    20u | (0u<<8) | (10u<<16), 19u | (0u<<8) | (10u<<16), 19u | (10u<<8) | (20u<<16), 18u | (9u<<8) | (19u<<16),  9u | (0u<<8) | (10u<<16),
    18u | (0u<<8) | (9u<<16),  17u | (0u<<8) | (9u<<16),  17u | (9u<<8) | (18u<<16),  16u | (8u<<8) | (17u<<16),  8u | (0u<<8) | (9u<<16),
    16u | (0u<<8) | (8u<<16),   7u | (0u<<8) | (8u<<16),
     6u | (0u<<8) | (7u<<16),   5u | (0u<<8) | (6u<<16),   4u | (0u<<8) | (5u<<16),   3u | (0u<<8) | (4u<<16),
     2u | (0u<<8) | (3u<<16),   1u | (0u<<8) | (2u<<16),   0u | (0u<<8) | (1u<<16)
};

// ---------------------------------------------------------------------------
// Base-ISA tensor helpers: mma.sync m16n8k16 bf16
// ---------------------------------------------------------------------------
__device__ __forceinline__ uint32_t smem_u32(const void* p) {
    uint32_t a;
    asm("{ .reg .u64 t; cvta.to.shared.u64 t, %1; cvt.u32.u64 %0, t; }" : "=r"(a) : "l"(p));
    return a;
}
__device__ __forceinline__ void ldm4(uint32_t* r, uint32_t addr) {
    asm volatile("ldmatrix.sync.aligned.m8n8.x4.shared.b16 {%0,%1,%2,%3}, [%4];"
                 : "=r"(r[0]), "=r"(r[1]), "=r"(r[2]), "=r"(r[3]) : "r"(addr));
}
__device__ __forceinline__ void ldm4t(uint32_t* r, uint32_t addr) {
    asm volatile("ldmatrix.sync.aligned.m8n8.x4.trans.shared.b16 {%0,%1,%2,%3}, [%4];"
                 : "=r"(r[0]), "=r"(r[1]), "=r"(r[2]), "=r"(r[3]) : "r"(addr));
}
__device__ __forceinline__ void mma_bf16(float* d, const uint32_t* a, uint32_t b0, uint32_t b1) {
    asm volatile("mma.sync.aligned.m16n8k16.row.col.f32.bf16.bf16.f32 "
                 "{%0,%1,%2,%3}, {%4,%5,%6,%7}, {%8,%9}, {%0,%1,%2,%3};"
                 : "+f"(d[0]), "+f"(d[1]), "+f"(d[2]), "+f"(d[3])
                 : "r"(a[0]), "r"(a[1]), "r"(a[2]), "r"(a[3]), "r"(b0), "r"(b1));
}
__device__ __forceinline__ uint32_t pack2(__nv_bfloat16 lo, __nv_bfloat16 hi) {
    return (uint32_t)__bfloat16_as_ushort(lo) | ((uint32_t)__bfloat16_as_ushort(hi) << 16);
}
__device__ __forceinline__ void split4(float4 v, uint2& hi, uint2& lo) {
    __nv_bfloat16 hx = __float2bfloat16(v.x), hy = __float2bfloat16(v.y);
    __nv_bfloat16 hz = __float2bfloat16(v.z), hw = __float2bfloat16(v.w);
    hi.x = pack2(hx, hy);
    hi.y = pack2(hz, hw);
    lo.x = pack2(__float2bfloat16(v.x - __bfloat162float(hx)),
                 __float2bfloat16(v.y - __bfloat162float(hy)));
    lo.y = pack2(__float2bfloat16(v.z - __bfloat162float(hz)),
                 __float2bfloat16(v.w - __bfloat162float(hw)));
}
__device__ __forceinline__ void split2(float a, float b, uint32_t& hi, uint32_t& lo) {
    __nv_bfloat16 ha = __float2bfloat16(a), hb = __float2bfloat16(b);
    hi = pack2(ha, hb);
    lo = pack2(__float2bfloat16(a - __bfloat162float(ha)),
               __float2bfloat16(b - __bfloat162float(hb)));
}

// ---------------------------------------------------------------------------
// Kernel 0: transpose + hi/lo split the weights (Wq pre-scaled by C^-0.5).
// ---------------------------------------------------------------------------
__global__ void __launch_bounds__(256) wt_split_kernel(
    const float* __restrict__ Wq, const float* __restrict__ Wk, const float* __restrict__ Wv)
{
    const int mat = blockIdx.y;
    const float* W = (mat == 0) ? Wq : (mat == 1) ? Wk : Wv;
    const int idx = blockIdx.x * 256 + threadIdx.x;
    const int n = idx >> 10, k = idx & 1023;
    float w = W[(size_t)k * H_ + n];
    if (mat == 0) w *= 0.03125f;
    __nv_bfloat16 hi = __float2bfloat16(w);
    float lo = w - __bfloat162float(hi);
    g_wt_hi[(size_t)mat * H_ * C_ + idx] = hi;
    g_wt_lo[(size_t)mat * H_ * C_ + idx] = __float2bfloat16(lo);
}

// ---------------------------------------------------------------------------
// Kernel 1: QKV projection via mma.sync bf16 hi/lo split (unchanged R15).
// ---------------------------------------------------------------------------
__global__ void __launch_bounds__(256) qkv_mma_kernel(const float* __restrict__ x)
{
    __shared__ __align__(128) char sm[49152];
    const uint32_t sb = smem_u32(sm);
    const int t = threadIdx.x, lane = t & 31, w = t >> 5;
    const int wm = w & 1, wn = w >> 1;
    const int m0 = blockIdx.x * 64, mat = blockIdx.y;
    __nv_bfloat16* ohi = (mat == 0) ? g_qhi : (mat == 1) ? g_khi : g_vhi;
    __nv_bfloat16* olo = (mat == 0) ? g_qlo : (mat == 1) ? g_klo : g_vlo;
    const __nv_bfloat16* wth = g_wt_hi + (size_t)mat * H_ * C_;
    const __nv_bfloat16* wtl = g_wt_lo + (size_t)mat * H_ * C_;

    float acc[2][4][4] = {};

    const int a_r  = wm * 32 + (lane & 7) + ((lane & 8) ? 8 : 0);
    const int a_kb = (lane & 16) ? 16 : 0;
    const uint32_t a_sw = ((uint32_t)(a_r & 7)) << 4;
    const int b_n  = wn * 32 + (lane & 7) + ((lane & 16) ? 8 : 0);
    const int b_kb = (lane & 8) ? 16 : 0;
    const uint32_t b_sw = ((uint32_t)(b_n & 7)) << 4;

    float4 pa[4];
    uint4  phb[4], plb[4];
    #pragma unroll
    for (int i = 0; i < 4; i++) {
        int idx = t + i * 256, r = idx >> 4, k4 = idx & 15;
        pa[i] = *(const float4*)(x + (size_t)(m0 + r) * C_ + k4 * 4);
    }
    #pragma unroll
    for (int i = 0; i < 4; i++) {
        int idx = t + i * 256, n = idx >> 3, k8 = idx & 7;
        phb[i] = *(const uint4*)(wth + (size_t)n * C_ + k8 * 8);
        plb[i] = *(const uint4*)(wtl + (size_t)n * C_ + k8 * 8);
    }

    for (int c = 0; c < 16; c++) {
        __syncthreads();
        #pragma unroll
        for (int i = 0; i < 4; i++) {
            int idx = t + i * 256, r = idx >> 4, k4 = idx & 15;
            uint2 hi, lo; split4(pa[i], hi, lo);
            uint32_t off = (uint32_t)(r * 128) + (((uint32_t)(k4 * 8)) ^ (((uint32_t)r & 7) << 4));
            *(uint2*)(sm + off)        = hi;
            *(uint2*)(sm + 8192 + off) = lo;
        }
        #pragma unroll
        for (int i = 0; i < 4; i++) {
            int idx = t + i * 256, n = idx >> 3, k8 = idx & 7;
            uint32_t off = (uint32_t)(n * 128) + (((uint32_t)(k8 * 16)) ^ (((uint32_t)n & 7) << 4));
            *(uint4*)(sm + 16384 + off) = phb[i];
            *(uint4*)(sm + 32768 + off) = plb[i];
        }
        __syncthreads();

        if (c < 15) {
            const int k0 = (c + 1) * 64;
            #pragma unroll
            for (int i = 0; i < 4; i++) {
                int idx = t + i * 256, r = idx >> 4, k4 = idx & 15;
                pa[i] = *(const float4*)(x + (size_t)(m0 + r) * C_ + k0 + k4 * 4);
            }
            #pragma unroll
            for (int i = 0; i < 4; i++) {
                int idx = t + i * 256, n = idx >> 3, k8 = idx & 7;
                phb[i] = *(const uint4*)(wth + (size_t)n * C_ + k0 + k8 * 8);
                plb[i] = *(const uint4*)(wtl + (size_t)n * C_ + k0 + k8 * 8);
            }
        }

        #pragma unroll
        for (int ks = 0; ks < 4; ks++) {
            uint32_t ah[2][4], al[2][4];
            #pragma unroll
            for (int f = 0; f < 2; f++) {
                uint32_t off = (uint32_t)((a_r + f * 16) * 128) + (((uint32_t)(ks * 32 + a_kb)) ^ a_sw);
                ldm4(ah[f], sb + off);
                ldm4(al[f], sb + 8192 + off);
            }
            #pragma unroll
            for (int half = 0; half < 2; half++) {
                uint32_t off = (uint32_t)((b_n + half * 16) * 128) + (((uint32_t)(ks * 32 + b_kb)) ^ b_sw);
                uint32_t bh[4], bl[4];
                ldm4(bh, sb + 16384 + off);
                ldm4(bl, sb + 32768 + off);
                #pragma unroll
                for (int f = 0; f < 2; f++) {
                    const int j0 = half * 2;
                    mma_bf16(acc[f][j0],     ah[f], bh[0], bh[1]);
                    mma_bf16(acc[f][j0],     ah[f], bl[0], bl[1]);
                    mma_bf16(acc[f][j0],     al[f], bh[0], bh[1]);
                    mma_bf16(acc[f][j0 + 1], ah[f], bh[2], bh[3]);
                    mma_bf16(acc[f][j0 + 1], ah[f], bl[2], bl[3]);
                    mma_bf16(acc[f][j0 + 1], al[f], bh[2], bh[3]);
                }
            }
        }
    }

    const int r = lane >> 2, cc = lane & 3;
    uint32_t* ohi32 = (uint32_t*)ohi;
    uint32_t* olo32 = (uint32_t*)olo;
    #pragma unroll
    for (int f = 0; f < 2; f++) {
        int row = m0 + wm * 32 + f * 16 + r;
        #pragma unroll
        for (int j = 0; j < 4; j++) {
            int col = wn * 32 + j * 8 + cc * 2;
            uint32_t h0, l0, h1, l1;
            split2(acc[f][j][0], acc[f][j][1], h0, l0);
            split2(acc[f][j][2], acc[f][j][3], h1, l1);
            ohi32[(size_t)row * 64 + (col >> 1)]       = h0;
            olo32[(size_t)row * 64 + (col >> 1)]       = l0;
            ohi32[(size_t)(row + 8) * 64 + (col >> 1)] = h1;
            olo32[(size_t)(row + 8) * 64 + (col >> 1)] = l1;
        }
    }
}

// ---------------------------------------------------------------------------
// Kernel 2: flash attention — warp-per-row-group layout.
// 128 threads = 4 warps. Warp wm owns rows wm*16..+15 over ALL 64 keys and
// ALL 128 output dims: softmax fully in-warp, P re-packed in registers
// (C-frag -> A-frag), no P smem, 2 syncs/tile. smem 96KB -> 2 CTAs/SM.
// Split-K units from g_units (grid 192 x 128 thr); combine as before.
// ---------------------------------------------------------------------------
#define SQ_HI 0
#define SQ_LO 16384
#define SK_HI 32768
#define SK_LO 49152
#define SV_HI 65536
#define SV_LO 81920
#define ATT_SMEM 98304

__global__ void __launch_bounds__(128) attn_mma_kernel(float* __restrict__ out)
{
    extern __shared__ __align__(16) char sm[];
    const uint32_t sb = smem_u32(sm);
    const int t = threadIdx.x, lane = t & 31, wm = t >> 5;
    const int g = blockIdx.x;
    const int b = g & 3;
    const uint32_t ent = g_units[g >> 2];
    const int qt = (int)(ent & 255u);
    const int t0 = (int)((ent >> 8) & 255u);
    const int t1 = (int)((ent >> 16) & 255u);
    const bool full = (t0 == 0) && (t1 == qt + 1);
    const int slot = (t0 == 0) ? 0 : 1;
    const int r = lane >> 2, cc = lane & 3;

    // ---- load Q tile (pre-split bf16, scale folded into Wq) ----
    const size_t qrow0 = (size_t)b * T_ + (size_t)qt * 64;
    #pragma unroll
    for (int i = 0; i < 16; i++) {
        int idx = t + i * 128;
        int a = idx >> 10, rem = idx & 1023, rr = rem >> 4, g16 = rem & 15;
        const __nv_bfloat16* src = (a == 0) ? g_qhi : g_qlo;
        uint4 v = *(const uint4*)(src + (qrow0 + rr) * H_ + g16 * 8);
        uint32_t off = (uint32_t)(a * 16384) + (uint32_t)(rr * 256) +
                       (((uint32_t)(g16 * 16)) ^ (((uint32_t)rr & 7) << 4));
        *(uint4*)(sm + off) = v;
    }

    float mrow0 = -1e30f, mrow1 = -1e30f, lrow0 = 0.f, lrow1 = 0.f;
    float o[16][4] = {};

    // loop-invariant ldmatrix lane addressing
    const int qa_r  = wm * 16 + (lane & 7) + ((lane & 8) ? 8 : 0);   // Q A-frag rows
    const int qa_kb = (lane & 16) ? 16 : 0;
    const uint32_t qa_sw = ((uint32_t)(qa_r & 7)) << 4;
    const int kb_n  = (lane & 7) + ((lane & 16) ? 8 : 0);            // K B-frag n (per n16 group)
    const int kb_kb = (lane & 8) ? 16 : 0;
    const uint32_t kb_sw = ((uint32_t)(kb_n & 7)) << 4;
    const int vb_k  = (lane & 7) + ((lane & 8) ? 8 : 0);             // V key (trans)
    const int vb_db = (lane & 16) ? 16 : 0;
    const int row0  = wm * 16 + r;

    for (int j = t0; j < t1; j++) {
        __syncthreads();   // all warps done reading prev K/V
        const size_t krow0 = (size_t)b * T_ + (size_t)j * 64;
        #pragma unroll
        for (int i = 0; i < 32; i++) {
            int idx = t + i * 128;
            int a = idx >> 10, rem = idx & 1023, rr = rem >> 4, g16 = rem & 15;
            const __nv_bfloat16* src = (a == 0) ? g_khi : (a == 1) ? g_klo : (a == 2) ? g_vhi : g_vlo;
            uint4 v = *(const uint4*)(src + (krow0 + rr) * H_ + g16 * 8);
            uint32_t off = (uint32_t)(SK_HI + a * 16384) + (uint32_t)(rr * 256) +
                           (((uint32_t)(g16 * 16)) ^ (((uint32_t)rr & 7) << 4));
            *(uint4*)(sm + off) = v;
        }
        __syncthreads();

        // ---- S = Q K^T : warp computes its 16 rows x all 64 keys ----
        float s[8][4] = {};
        #pragma unroll
        for (int ks = 0; ks < 8; ks++) {
            uint32_t qoff = (uint32_t)(qa_r * 256) + (((uint32_t)(ks * 32 + qa_kb)) ^ qa_sw);
            uint32_t qh[4], ql[4];
            ldm4(qh, sb + SQ_HI + qoff);
            ldm4(ql, sb + SQ_LO + qoff);
            #pragma unroll
            for (int hn = 0; hn < 4; hn++) {           // 4 n16-groups = 64 keys
                uint32_t koff = (uint32_t)((kb_n + hn * 16) * 256) + (((uint32_t)(ks * 32 + kb_kb)) ^ kb_sw);
                uint32_t kh[4], kl[4];
                ldm4(kh, sb + SK_HI + koff);
                ldm4(kl, sb + SK_LO + koff);
                const int j0 = hn * 2;
                mma_bf16(s[j0],     qh, kh[0], kh[1]);
                mma_bf16(s[j0],     qh, kl[0], kl[1]);
                mma_bf16(s[j0],     ql, kh[0], kh[1]);
                mma_bf16(s[j0 + 1], qh, kh[2], kh[3]);
                mma_bf16(s[j0 + 1], qh, kl[2], kl[3]);
                mma_bf16(s[j0 + 1], ql, kh[2], kh[3]);
            }
        }

        // ---- causal mask (diagonal tile only) ----
        if (j == qt) {
            #pragma unroll
            for (int jf = 0; jf < 8; jf++) {
                int col = jf * 8 + cc * 2;
                if (col     > row0)     s[jf][0] = -1e30f;
                if (col + 1 > row0)     s[jf][1] = -1e30f;
                if (col     > row0 + 8) s[jf][2] = -1e30f;
                if (col + 1 > row0 + 8) s[jf][3] = -1e30f;
            }
        }

        // ---- online softmax, fully in-warp ----
        float mx0 = -1e30f, mx1 = -1e30f;
        #pragma unroll
        for (int jf = 0; jf < 8; jf++) {
            mx0 = fmaxf(mx0, fmaxf(s[jf][0], s[jf][1]));
            mx1 = fmaxf(mx1, fmaxf(s[jf][2], s[jf][3]));
        }
        mx0 = fmaxf(mx0, __shfl_xor_sync(0xffffffffu, mx0, 1));
        mx0 = fmaxf(mx0, __shfl_xor_sync(0xffffffffu, mx0, 2));
        mx1 = fmaxf(mx1, __shfl_xor_sync(0xffffffffu, mx1, 1));
        mx1 = fmaxf(mx1, __shfl_xor_sync(0xffffffffu, mx1, 2));
        float mn0 = fmaxf(mrow0, mx0);
        float mn1 = fmaxf(mrow1, mx1);
        float alpha0 = __expf(mrow0 - mn0), alpha1 = __expf(mrow1 - mn1);
        mrow0 = mn0; mrow1 = mn1;

        // exp + in-register split into hi/lo packed A-operand halves
        uint32_t pch[8], pcl[8];   // per n8-frag: pack(c0,c1) rows r / (c2,c3) rows r+8
        uint32_t pdh[8], pdl[8];
        float sum0 = 0.f, sum1 = 0.f;
        #pragma unroll
        for (int jf = 0; jf < 8; jf++) {
            float p0 = __expf(s[jf][0] - mn0);
            float p1 = __expf(s[jf][1] - mn0);
            float p2 = __expf(s[jf][2] - mn1);
            float p3 = __expf(s[jf][3] - mn1);
            sum0 += p0 + p1; sum1 += p2 + p3;
            split2(p0, p1, pch[jf], pcl[jf]);
            split2(p2, p3, pdh[jf], pdl[jf]);
        }
        sum0 += __shfl_xor_sync(0xffffffffu, sum0, 1);
        sum0 += __shfl_xor_sync(0xffffffffu, sum0, 2);
        sum1 += __shfl_xor_sync(0xffffffffu, sum1, 1);
        sum1 += __shfl_xor_sync(0xffffffffu, sum1, 2);
        lrow0 = lrow0 * alpha0 + sum0;
        lrow1 = lrow1 * alpha1 + sum1;

        #pragma unroll
        for (int jj = 0; jj < 16; jj++) {
            o[jj][0] *= alpha0; o[jj][1] *= alpha0;
            o[jj][2] *= alpha1; o[jj][3] *= alpha1;
        }

        // ---- O += P V : A-frags assembled from registers ----
        #pragma unroll
        for (int ks = 0; ks < 4; ks++) {
            // A frag for keys 16ks..16ks+15: a0/a1 from n8-frag 2ks, a2/a3 from 2ks+1
            uint32_t ph[4] = { pch[2*ks], pdh[2*ks], pch[2*ks+1], pdh[2*ks+1] };
            uint32_t pl[4] = { pcl[2*ks], pdl[2*ks], pcl[2*ks+1], pdl[2*ks+1] };
            const int key = ks * 16 + vb_k;
            const uint32_t v_sw = ((uint32_t)(key & 7)) << 4;
            #pragma unroll
            for (int dd = 0; dd < 8; dd++) {           // 8 n16-groups = 128 dims
                uint32_t voff = (uint32_t)(key * 256) + (((uint32_t)(dd * 32 + vb_db)) ^ v_sw);
                uint32_t vh[4], vl[4];
                ldm4t(vh, sb + SV_HI + voff);
                ldm4t(vl, sb + SV_LO + voff);
                const int jj = dd * 2;
                mma_bf16(o[jj],     ph, vh[0], vh[1]);
                mma_bf16(o[jj],     ph, vl[0], vl[1]);
                mma_bf16(o[jj],     pl, vh[0], vh[1]);
                mma_bf16(o[jj + 1], ph, vh[2], vh[3]);
                mma_bf16(o[jj + 1], ph, vl[2], vl[3]);
                mma_bf16(o[jj + 1], pl, vh[2], vh[3]);
            }
        }
    }

    // ---- epilogue ----
    const size_t grow0 = qrow0 + row0;
    if (full) {
        const float inv0 = 1.f / lrow0, inv1 = 1.f / lrow1;
        #pragma unroll
        for (int jj = 0; jj < 16; jj++) {
            int col = jj * 8 + cc * 2;
            *(float2*)(out + grow0 * H_ + col) =
                make_float2(o[jj][0] * inv0, o[jj][1] * inv0);
            *(float2*)(out + (grow0 + 8) * H_ + col) =
                make_float2(o[jj][2] * inv1, o[jj][3] * inv1);
        }
    } else {
        float* po = g_po + (size_t)slot * BT_ * H_;
        #pragma unroll
        for (int jj = 0; jj < 16; jj++) {
            int col = jj * 8 + cc * 2;
            *(float2*)(po + grow0 * H_ + col)       = make_float2(o[jj][0], o[jj][1]);
            *(float2*)(po + (grow0 + 8) * H_ + col) = make_float2(o[jj][2], o[jj][3]);
        }
        if (cc == 0) {
            g_ml[(size_t)slot * BT_ + grow0]     = make_float2(mrow0, lrow0);
            g_ml[(size_t)slot * BT_ + grow0 + 8] = make_float2(mrow1, lrow1);
        }
    }
}

// ---------------------------------------------------------------------------
// Kernel 3: merge the two split-K partials for heavy rows (qt >= 16).
// ---------------------------------------------------------------------------
__global__ void __launch_bounds__(256) attn_combine_kernel(float* __restrict__ out)
{
    int idx = blockIdx.x * 256 + threadIdx.x;
    int b = idx >> 15;
    int rem = idx & 32767;
    int rl = rem >> 5, c4 = rem & 31;
    size_t row = (size_t)b * T_ + 1024 + rl;
    float2 ml0 = g_ml[row];
    float2 ml1 = g_ml[BT_ + row];
    float M = fmaxf(ml0.x, ml1.x);
    float a0 = __expf(ml0.x - M), a1 = __expf(ml1.x - M);
    float inv = 1.f / (ml0.y * a0 + ml1.y * a1);
    float4 p0 = *(const float4*)(g_po + row * H_ + c4 * 4);
    float4 p1 = *(const float4*)(g_po + (size_t)BT_ * H_ + row * H_ + c4 * 4);
    *(float4*)(out + row * H_ + c4 * 4) = make_float4(
        (p0.x * a0 + p1.x * a1) * inv,
        (p0.y * a0 + p1.y * a1) * inv,
        (p0.z * a0 + p1.z * a1) * inv,
        (p0.w * a0 + p1.w * a1) * inv);
}

// ---------------------------------------------------------------------------
// Launch
// ---------------------------------------------------------------------------
extern "C" void kernel_launch(void* const* d_in, const int* in_sizes, int n_in,
                              void* d_out, int out_size)
{
    (void)in_sizes; (void)n_in; (void)out_size;
    const float* x  = (const float*)d_in[0];
    const float* Wq = (const float*)d_in[1];
    const float* Wk = (const float*)d_in[2];
    const float* Wv = (const float*)d_in[3];
    float* out = (float*)d_out;

    wt_split_kernel<<<dim3(512, 3), 256>>>(Wq, Wk, Wv);
    qkv_mma_kernel<<<dim3(128, 3), 256>>>(x);

    cudaFuncSetAttribute(attn_mma_kernel, cudaFuncAttributeMaxDynamicSharedMemorySize, ATT_SMEM);
    attn_mma_kernel<<<192, 128, ATT_SMEM>>>(out);

    attn_combine_kernel<<<512, 256>>>(out);
}

// round 17
// speedup vs baseline: 1.3380x; 1.3380x over previous
#include <cuda_runtime.h>
#include <cuda_bf16.h>
#include <cuda_fp16.h>
#include <cstdint>

// Problem constants
#define B_   4
#define T_   2048
#define C_   1024
#define H_   128
#define BT_  (B_ * T_)

// ---------------------------------------------------------------------------
// Scratch (__device__ globals per alloc rules)
// ---------------------------------------------------------------------------
// Q/K/V stored as single fp16 (attention runs single-term fp16 HMMA)
__device__ __half g_q16[BT_ * H_];
__device__ __half g_k16[BT_ * H_];
__device__ __half g_v16[BT_ * H_];
// Transposed + hi/lo-split weights: [3 mats][128 n][1024 k] bf16 (Wq pre-scaled)
__device__ __nv_bfloat16 g_wt_hi[3 * H_ * C_];
__device__ __nv_bfloat16 g_wt_lo[3 * H_ * C_];
// Split-K partials
__device__ float  g_po[2 * BT_ * H_];
__device__ float2 g_ml[2 * BT_];

// Work-unit table: 48 units per batch, globally sorted by descending tile
// count. entry = qt | (t0 << 8) | (t1 << 16); unit covers KV tiles [t0, t1).
__device__ const uint32_t g_units[48] = {
    31u | (0u<<8) | (16u<<16), 31u | (16u<<8) | (32u<<16), 30u | (15u<<8) | (31u<<16), 15u | (0u<<8) | (16u<<16),
    30u | (0u<<8) | (15u<<16), 29u | (0u<<8) | (15u<<16), 29u | (15u<<8) | (30u<<16), 28u | (14u<<8) | (29u<<16), 14u | (0u<<8) | (15u<<16),
    28u | (0u<<8) | (14u<<16), 27u | (0u<<8) | (14u<<16), 27u | (14u<<8) | (28u<<16), 26u | (13u<<8) | (27u<<16), 13u | (0u<<8) | (14u<<16),
    26u | (0u<<8) | (13u<<16), 25u | (0u<<8) | (13u<<16), 25u | (13u<<8) | (26u<<16), 24u | (12u<<8) | (25u<<16), 12u | (0u<<8) | (13u<<16),
    24u | (0u<<8) | (12u<<16), 23u | (0u<<8) | (12u<<16), 23u | (12u<<8) | (24u<<16), 22u | (11u<<8) | (23u<<16), 11u | (0u<<8) | (12u<<16),
    22u | (0u<<8) | (11u<<16), 21u | (0u<<8) | (11u<<16), 21u | (11u<<8) | (22u<<16), 20u | (10u<<8) | (21u<<16), 10u | (0u<<8) | (11u<<16),
    20u | (0u<<8) | (10u<<16), 19u | (0u<<8) | (10u<<16), 19u | (10u<<8) | (20u<<16), 18u | (9u<<8) | (19u<<16),  9u | (0u<<8) | (10u<<16),
    18u | (0u<<8) | (9u<<16),  17u | (0u<<8) | (9u<<16),  17u | (9u<<8) | (18u<<16),  16u | (8u<<8) | (17u<<16),  8u | (0u<<8) | (9u<<16),
    16u | (0u<<8) | (8u<<16),   7u | (0u<<8) | (8u<<16),
     6u | (0u<<8) | (7u<<16),   5u | (0u<<8) | (6u<<16),   4u | (0u<<8) | (5u<<16),   3u | (0u<<8) | (4u<<16),
     2u | (0u<<8) | (3u<<16),   1u | (0u<<8) | (2u<<16),   0u | (0u<<8) | (1u<<16)
};

// ---------------------------------------------------------------------------
// Tensor helpers
// ---------------------------------------------------------------------------
__device__ __forceinline__ uint32_t smem_u32(const void* p) {
    uint32_t a;
    asm("{ .reg .u64 t; cvta.to.shared.u64 t, %1; cvt.u32.u64 %0, t; }" : "=r"(a) : "l"(p));
    return a;
}
__device__ __forceinline__ void ldm4(uint32_t* r, uint32_t addr) {
    asm volatile("ldmatrix.sync.aligned.m8n8.x4.shared.b16 {%0,%1,%2,%3}, [%4];"
                 : "=r"(r[0]), "=r"(r[1]), "=r"(r[2]), "=r"(r[3]) : "r"(addr));
}
__device__ __forceinline__ void ldm4t(uint32_t* r, uint32_t addr) {
    asm volatile("ldmatrix.sync.aligned.m8n8.x4.trans.shared.b16 {%0,%1,%2,%3}, [%4];"
                 : "=r"(r[0]), "=r"(r[1]), "=r"(r[2]), "=r"(r[3]) : "r"(addr));
}
__device__ __forceinline__ void mma_bf16(float* d, const uint32_t* a, uint32_t b0, uint32_t b1) {
    asm volatile("mma.sync.aligned.m16n8k16.row.col.f32.bf16.bf16.f32 "
                 "{%0,%1,%2,%3}, {%4,%5,%6,%7}, {%8,%9}, {%0,%1,%2,%3};"
                 : "+f"(d[0]), "+f"(d[1]), "+f"(d[2]), "+f"(d[3])
                 : "r"(a[0]), "r"(a[1]), "r"(a[2]), "r"(a[3]), "r"(b0), "r"(b1));
}
__device__ __forceinline__ void mma_f16(float* d, const uint32_t* a, uint32_t b0, uint32_t b1) {
    asm volatile("mma.sync.aligned.m16n8k16.row.col.f32.f16.f16.f32 "
                 "{%0,%1,%2,%3}, {%4,%5,%6,%7}, {%8,%9}, {%0,%1,%2,%3};"
                 : "+f"(d[0]), "+f"(d[1]), "+f"(d[2]), "+f"(d[3])
                 : "r"(a[0]), "r"(a[1]), "r"(a[2]), "r"(a[3]), "r"(b0), "r"(b1));
}
__device__ __forceinline__ uint32_t pack2(__nv_bfloat16 lo, __nv_bfloat16 hi) {
    return (uint32_t)__bfloat16_as_ushort(lo) | ((uint32_t)__bfloat16_as_ushort(hi) << 16);
}
__device__ __forceinline__ uint32_t pack2h(__half lo, __half hi) {
    return (uint32_t)__half_as_ushort(lo) | ((uint32_t)__half_as_ushort(hi) << 16);
}
__device__ __forceinline__ void split4(float4 v, uint2& hi, uint2& lo) {
    __nv_bfloat16 hx = __float2bfloat16(v.x), hy = __float2bfloat16(v.y);
    __nv_bfloat16 hz = __float2bfloat16(v.z), hw = __float2bfloat16(v.w);
    hi.x = pack2(hx, hy);
    hi.y = pack2(hz, hw);
    lo.x = pack2(__float2bfloat16(v.x - __bfloat162float(hx)),
                 __float2bfloat16(v.y - __bfloat162float(hy)));
    lo.y = pack2(__float2bfloat16(v.z - __bfloat162float(hz)),
                 __float2bfloat16(v.w - __bfloat162float(hw)));
}

// ---------------------------------------------------------------------------
// Kernel 0: transpose + hi/lo split the weights (Wq pre-scaled by C^-0.5).
// ---------------------------------------------------------------------------
__global__ void __launch_bounds__(256) wt_split_kernel(
    const float* __restrict__ Wq, const float* __restrict__ Wk, const float* __restrict__ Wv)
{
    const int mat = blockIdx.y;
    const float* W = (mat == 0) ? Wq : (mat == 1) ? Wk : Wv;
    const int idx = blockIdx.x * 256 + threadIdx.x;
    const int n = idx >> 10, k = idx & 1023;
    float w = W[(size_t)k * H_ + n];
    if (mat == 0) w *= 0.03125f;
    __nv_bfloat16 hi = __float2bfloat16(w);
    float lo = w - __bfloat162float(hi);
    g_wt_hi[(size_t)mat * H_ * C_ + idx] = hi;
    g_wt_lo[(size_t)mat * H_ * C_ + idx] = __float2bfloat16(lo);
}

// ---------------------------------------------------------------------------
// Kernel 1: QKV projection via mma.sync bf16 hi/lo split (3-term, fp32 acc).
// Epilogue now stores single fp16. Otherwise unchanged from R15/R16.
// ---------------------------------------------------------------------------
__global__ void __launch_bounds__(256) qkv_mma_kernel(const float* __restrict__ x)
{
    __shared__ __align__(128) char sm[49152];
    const uint32_t sb = smem_u32(sm);
    const int t = threadIdx.x, lane = t & 31, w = t >> 5;
    const int wm = w & 1, wn = w >> 1;
    const int m0 = blockIdx.x * 64, mat = blockIdx.y;
    __half* out16 = (mat == 0) ? g_q16 : (mat == 1) ? g_k16 : g_v16;
    const __nv_bfloat16* wth = g_wt_hi + (size_t)mat * H_ * C_;
    const __nv_bfloat16* wtl = g_wt_lo + (size_t)mat * H_ * C_;

    float acc[2][4][4] = {};

    const int a_r  = wm * 32 + (lane & 7) + ((lane & 8) ? 8 : 0);
    const int a_kb = (lane & 16) ? 16 : 0;
    const uint32_t a_sw = ((uint32_t)(a_r & 7)) << 4;
    const int b_n  = wn * 32 + (lane & 7) + ((lane & 16) ? 8 : 0);
    const int b_kb = (lane & 8) ? 16 : 0;
    const uint32_t b_sw = ((uint32_t)(b_n & 7)) << 4;

    float4 pa[4];
    uint4  phb[4], plb[4];
    #pragma unroll
    for (int i = 0; i < 4; i++) {
        int idx = t + i * 256, r = idx >> 4, k4 = idx & 15;
        pa[i] = *(const float4*)(x + (size_t)(m0 + r) * C_ + k4 * 4);
    }
    #pragma unroll
    for (int i = 0; i < 4; i++) {
        int idx = t + i * 256, n = idx >> 3, k8 = idx & 7;
        phb[i] = *(const uint4*)(wth + (size_t)n * C_ + k8 * 8);
        plb[i] = *(const uint4*)(wtl + (size_t)n * C_ + k8 * 8);
    }

    for (int c = 0; c < 16; c++) {
        __syncthreads();
        #pragma unroll
        for (int i = 0; i < 4; i++) {
            int idx = t + i * 256, r = idx >> 4, k4 = idx & 15;
            uint2 hi, lo; split4(pa[i], hi, lo);
            uint32_t off = (uint32_t)(r * 128) + (((uint32_t)(k4 * 8)) ^ (((uint32_t)r & 7) << 4));
            *(uint2*)(sm + off)        = hi;
            *(uint2*)(sm + 8192 + off) = lo;
        }
        #pragma unroll
        for (int i = 0; i < 4; i++) {
            int idx = t + i * 256, n = idx >> 3, k8 = idx & 7;
            uint32_t off = (uint32_t)(n * 128) + (((uint32_t)(k8 * 16)) ^ (((uint32_t)n & 7) << 4));
            *(uint4*)(sm + 16384 + off) = phb[i];
            *(uint4*)(sm + 32768 + off) = plb[i];
        }
        __syncthreads();

        if (c < 15) {
            const int k0 = (c + 1) * 64;
            #pragma unroll
            for (int i = 0; i < 4; i++) {
                int idx = t + i * 256, r = idx >> 4, k4 = idx & 15;
                pa[i] = *(const float4*)(x + (size_t)(m0 + r) * C_ + k0 + k4 * 4);
            }
            #pragma unroll
            for (int i = 0; i < 4; i++) {
                int idx = t + i * 256, n = idx >> 3, k8 = idx & 7;
                phb[i] = *(const uint4*)(wth + (size_t)n * C_ + k0 + k8 * 8);
                plb[i] = *(const uint4*)(wtl + (size_t)n * C_ + k0 + k8 * 8);
            }
        }

        #pragma unroll
        for (int ks = 0; ks < 4; ks++) {
            uint32_t ah[2][4], al[2][4];
            #pragma unroll
            for (int f = 0; f < 2; f++) {
                uint32_t off = (uint32_t)((a_r + f * 16) * 128) + (((uint32_t)(ks * 32 + a_kb)) ^ a_sw);
                ldm4(ah[f], sb + off);
                ldm4(al[f], sb + 8192 + off);
            }
            #pragma unroll
            for (int half = 0; half < 2; half++) {
                uint32_t off = (uint32_t)((b_n + half * 16) * 128) + (((uint32_t)(ks * 32 + b_kb)) ^ b_sw);
                uint32_t bh[4], bl[4];
                ldm4(bh, sb + 16384 + off);
                ldm4(bl, sb + 32768 + off);
                #pragma unroll
                for (int f = 0; f < 2; f++) {
                    const int j0 = half * 2;
                    mma_bf16(acc[f][j0],     ah[f], bh[0], bh[1]);
                    mma_bf16(acc[f][j0],     ah[f], bl[0], bl[1]);
                    mma_bf16(acc[f][j0],     al[f], bh[0], bh[1]);
                    mma_bf16(acc[f][j0 + 1], ah[f], bh[2], bh[3]);
                    mma_bf16(acc[f][j0 + 1], ah[f], bl[2], bl[3]);
                    mma_bf16(acc[f][j0 + 1], al[f], bh[2], bh[3]);
                }
            }
        }
    }

    // epilogue: fp32 -> single fp16
    const int r = lane >> 2, cc = lane & 3;
    uint32_t* o32 = (uint32_t*)out16;
    #pragma unroll
    for (int f = 0; f < 2; f++) {
        int row = m0 + wm * 32 + f * 16 + r;
        #pragma unroll
        for (int j = 0; j < 4; j++) {
            int col = wn * 32 + j * 8 + cc * 2;
            o32[(size_t)row * 64 + (col >> 1)] =
                pack2h(__float2half_rn(acc[f][j][0]), __float2half_rn(acc[f][j][1]));
            o32[(size_t)(row + 8) * 64 + (col >> 1)] =
                pack2h(__float2half_rn(acc[f][j][2]), __float2half_rn(acc[f][j][3]));
        }
    }
}

// ---------------------------------------------------------------------------
// Kernel 2: flash attention — single-term fp16 HMMA, warp-per-row-group.
// 128 threads = 4 warps; warp wm owns rows wm*16..+15 over all keys/dims.
// P stays in registers (C-frag -> A-frag repack). smem 48KB -> 4 CTAs/SM.
// ---------------------------------------------------------------------------
#define SQ_OFF 0
#define SK_OFF 16384
#define SV_OFF 32768
#define ATT_SMEM 49152

__global__ void __launch_bounds__(128) attn_mma_kernel(float* __restrict__ out)
{
    extern __shared__ __align__(16) char sm[];
    const uint32_t sb = smem_u32(sm);
    const int t = threadIdx.x, lane = t & 31, wm = t >> 5;
    const int g = blockIdx.x;
    const int b = g & 3;
    const uint32_t ent = g_units[g >> 2];
    const int qt = (int)(ent & 255u);
    const int t0 = (int)((ent >> 8) & 255u);
    const int t1 = (int)((ent >> 16) & 255u);
    const bool full = (t0 == 0) && (t1 == qt + 1);
    const int slot = (t0 == 0) ? 0 : 1;
    const int r = lane >> 2, cc = lane & 3;

    // ---- load Q tile (fp16, scale folded into Wq) ----
    const size_t qrow0 = (size_t)b * T_ + (size_t)qt * 64;
    #pragma unroll
    for (int i = 0; i < 8; i++) {
        int idx = t + i * 128;          // 1024 x 16B
        int rr = idx >> 4, g16 = idx & 15;
        uint4 v = *(const uint4*)(g_q16 + (qrow0 + rr) * H_ + g16 * 8);
        uint32_t off = (uint32_t)(rr * 256) + (((uint32_t)(g16 * 16)) ^ (((uint32_t)rr & 7) << 4));
        *(uint4*)(sm + SQ_OFF + off) = v;
    }

    float mrow0 = -1e30f, mrow1 = -1e30f, lrow0 = 0.f, lrow1 = 0.f;
    float o[16][4] = {};

    // loop-invariant ldmatrix lane addressing
    const int qa_r  = wm * 16 + (lane & 7) + ((lane & 8) ? 8 : 0);
    const int qa_kb = (lane & 16) ? 16 : 0;
    const uint32_t qa_sw = ((uint32_t)(qa_r & 7)) << 4;
    const int kb_n  = (lane & 7) + ((lane & 16) ? 8 : 0);
    const int kb_kb = (lane & 8) ? 16 : 0;
    const uint32_t kb_sw = ((uint32_t)(kb_n & 7)) << 4;
    const int vb_k  = (lane & 7) + ((lane & 8) ? 8 : 0);
    const int vb_db = (lane & 16) ? 16 : 0;
    const int row0  = wm * 16 + r;

    for (int j = t0; j < t1; j++) {
        __syncthreads();
        const size_t krow0 = (size_t)b * T_ + (size_t)j * 64;
        #pragma unroll
        for (int i = 0; i < 16; i++) {
            int idx = t + i * 128;      // 2048 x 16B over K then V
            int a = idx >> 10, rem = idx & 1023, rr = rem >> 4, g16 = rem & 15;
            const __half* src = (a == 0) ? g_k16 : g_v16;
            uint4 v = *(const uint4*)(src + (krow0 + rr) * H_ + g16 * 8);
            uint32_t off = (uint32_t)(SK_OFF + a * 16384) + (uint32_t)(rr * 256) +
                           (((uint32_t)(g16 * 16)) ^ (((uint32_t)rr & 7) << 4));
            *(uint4*)(sm + off) = v;
        }
        __syncthreads();

        // ---- S = Q K^T ----
        float s[8][4] = {};
        #pragma unroll
        for (int ks = 0; ks < 8; ks++) {
            uint32_t qoff = (uint32_t)(qa_r * 256) + (((uint32_t)(ks * 32 + qa_kb)) ^ qa_sw);
            uint32_t q[4];
            ldm4(q, sb + SQ_OFF + qoff);
            #pragma unroll
            for (int hn = 0; hn < 4; hn++) {
                uint32_t koff = (uint32_t)((kb_n + hn * 16) * 256) + (((uint32_t)(ks * 32 + kb_kb)) ^ kb_sw);
                uint32_t kf[4];
                ldm4(kf, sb + SK_OFF + koff);
                mma_f16(s[hn * 2],     q, kf[0], kf[1]);
                mma_f16(s[hn * 2 + 1], q, kf[2], kf[3]);
            }
        }

        // ---- causal mask (diagonal tile only) ----
        if (j == qt) {
            #pragma unroll
            for (int jf = 0; jf < 8; jf++) {
                int col = jf * 8 + cc * 2;
                if (col     > row0)     s[jf][0] = -1e30f;
                if (col + 1 > row0)     s[jf][1] = -1e30f;
                if (col     > row0 + 8) s[jf][2] = -1e30f;
                if (col + 1 > row0 + 8) s[jf][3] = -1e30f;
            }
        }

        // ---- online softmax, fully in-warp ----
        float mx0 = -1e30f, mx1 = -1e30f;
        #pragma unroll
        for (int jf = 0; jf < 8; jf++) {
            mx0 = fmaxf(mx0, fmaxf(s[jf][0], s[jf][1]));
            mx1 = fmaxf(mx1, fmaxf(s[jf][2], s[jf][3]));
        }
        mx0 = fmaxf(mx0, __shfl_xor_sync(0xffffffffu, mx0, 1));
        mx0 = fmaxf(mx0, __shfl_xor_sync(0xffffffffu, mx0, 2));
        mx1 = fmaxf(mx1, __shfl_xor_sync(0xffffffffu, mx1, 1));
        mx1 = fmaxf(mx1, __shfl_xor_sync(0xffffffffu, mx1, 2));
        float mn0 = fmaxf(mrow0, mx0);
        float mn1 = fmaxf(mrow1, mx1);
        float alpha0 = __expf(mrow0 - mn0), alpha1 = __expf(mrow1 - mn1);
        mrow0 = mn0; mrow1 = mn1;

        // exp + fp16 pack into A-operand halves (P never leaves registers)
        uint32_t pc[8], pd[8];
        float sum0 = 0.f, sum1 = 0.f;
        #pragma unroll
        for (int jf = 0; jf < 8; jf++) {
            float p0 = __expf(s[jf][0] - mn0);
            float p1 = __expf(s[jf][1] - mn0);
            float p2 = __expf(s[jf][2] - mn1);
            float p3 = __expf(s[jf][3] - mn1);
            sum0 += p0 + p1; sum1 += p2 + p3;
            pc[jf] = pack2h(__float2half_rn(p0), __float2half_rn(p1));
            pd[jf] = pack2h(__float2half_rn(p2), __float2half_rn(p3));
        }
        sum0 += __shfl_xor_sync(0xffffffffu, sum0, 1);
        sum0 += __shfl_xor_sync(0xffffffffu, sum0, 2);
        sum1 += __shfl_xor_sync(0xffffffffu, sum1, 1);
        sum1 += __shfl_xor_sync(0xffffffffu, sum1, 2);
        lrow0 = lrow0 * alpha0 + sum0;
        lrow1 = lrow1 * alpha1 + sum1;

        #pragma unroll
        for (int jj = 0; jj < 16; jj++) {
            o[jj][0] *= alpha0; o[jj][1] *= alpha0;
            o[jj][2] *= alpha1; o[jj][3] *= alpha1;
        }

        // ---- O += P V ----
        #pragma unroll
        for (int ks = 0; ks < 4; ks++) {
            uint32_t pf[4] = { pc[2*ks], pd[2*ks], pc[2*ks+1], pd[2*ks+1] };
            const int key = ks * 16 + vb_k;
            const uint32_t v_sw = ((uint32_t)(key & 7)) << 4;
            #pragma unroll
            for (int dd = 0; dd < 8; dd++) {
                uint32_t voff = (uint32_t)(key * 256) + (((uint32_t)(dd * 32 + vb_db)) ^ v_sw);
                uint32_t vf[4];
                ldm4t(vf, sb + SV_OFF + voff);
                mma_f16(o[dd * 2],     pf, vf[0], vf[1]);
                mma_f16(o[dd * 2 + 1], pf, vf[2], vf[3]);
            }
        }
    }

    // ---- epilogue ----
    const size_t grow0 = qrow0 + row0;
    if (full) {
        const float inv0 = 1.f / lrow0, inv1 = 1.f / lrow1;
        #pragma unroll
        for (int jj = 0; jj < 16; jj++) {
            int col = jj * 8 + cc * 2;
            *(float2*)(out + grow0 * H_ + col) =
                make_float2(o[jj][0] * inv0, o[jj][1] * inv0);
            *(float2*)(out + (grow0 + 8) * H_ + col) =
                make_float2(o[jj][2] * inv1, o[jj][3] * inv1);
        }
    } else {
        float* po = g_po + (size_t)slot * BT_ * H_;
        #pragma unroll
        for (int jj = 0; jj < 16; jj++) {
            int col = jj * 8 + cc * 2;
            *(float2*)(po + grow0 * H_ + col)       = make_float2(o[jj][0], o[jj][1]);
            *(float2*)(po + (grow0 + 8) * H_ + col) = make_float2(o[jj][2], o[jj][3]);
        }
        if (cc == 0) {
            g_ml[(size_t)slot * BT_ + grow0]     = make_float2(mrow0, lrow0);
            g_ml[(size_t)slot * BT_ + grow0 + 8] = make_float2(mrow1, lrow1);
        }
    }
}

// ---------------------------------------------------------------------------
// Kernel 3: merge the two split-K partials for heavy rows (qt >= 16).
// ---------------------------------------------------------------------------
__global__ void __launch_bounds__(256) attn_combine_kernel(float* __restrict__ out)
{
    int idx = blockIdx.x * 256 + threadIdx.x;
    int b = idx >> 15;
    int rem = idx & 32767;
    int rl = rem >> 5, c4 = rem & 31;
    size_t row = (size_t)b * T_ + 1024 + rl;
    float2 ml0 = g_ml[row];
    float2 ml1 = g_ml[BT_ + row];
    float M = fmaxf(ml0.x, ml1.x);
    float a0 = __expf(ml0.x - M), a1 = __expf(ml1.x - M);
    float inv = 1.f / (ml0.y * a0 + ml1.y * a1);
    float4 p0 = *(const float4*)(g_po + row * H_ + c4 * 4);
    float4 p1 = *(const float4*)(g_po + (size_t)BT_ * H_ + row * H_ + c4 * 4);
    *(float4*)(out + row * H_ + c4 * 4) = make_float4(
        (p0.x * a0 + p1.x * a1) * inv,
        (p0.y * a0 + p1.y * a1) * inv,
        (p0.z * a0 + p1.z * a1) * inv,
        (p0.w * a0 + p1.w * a1) * inv);
}

// ---------------------------------------------------------------------------
// Launch
// ---------------------------------------------------------------------------
extern "C" void kernel_launch(void* const* d_in, const int* in_sizes, int n_in,
                              void* d_out, int out_size)
{
    (void)in_sizes; (void)n_in; (void)out_size;
    const float* x  = (const float*)d_in[0];
    const float* Wq = (const float*)d_in[1];
    const float* Wk = (const float*)d_in[2];
    const float* Wv = (const float*)d_in[3];
    float* out = (float*)d_out;

    wt_split_kernel<<<dim3(512, 3), 256>>>(Wq, Wk, Wv);
    qkv_mma_kernel<<<dim3(128, 3), 256>>>(x);

    cudaFuncSetAttribute(attn_mma_kernel, cudaFuncAttributeMaxDynamicSharedMemorySize, ATT_SMEM);
    attn_mma_kernel<<<192, 128, ATT_SMEM>>>(out);

    attn_combine_kernel<<<512, 256>>>(out);
}